// round 13
// baseline (speedup 1.0000x reference)
#include <cuda_runtime.h>
#include <cuda_fp16.h>
#include <math.h>
#include <stdint.h>

#define NTOK 2048
#define NB 4
#define DDIM 512
#define D1 1024
#define EDIM 512
#define ROWS (NB * NTOK)   // 8192
#define GAMMA_F 0.999f

// ---------------- scratch (device globals: allocation-free) ----------------
__device__ float  g_u  [ROWS * D1];
__device__ float  g_v  [ROWS * D1];
__device__ float  g_arr[NTOK * D1];
__device__ __half g_xnh [ROWS * DDIM];
__device__ __half g_yh  [ROWS * D1];
__device__ __half g_Wuh[DDIM * D1];
__device__ __half g_Wvh[DDIM * D1];
__device__ __half g_Woh[D1 * DDIM];
__device__ __half g_W1h[EDIM * EDIM];
__device__ __half g_W2h[EDIM * EDIM];
__device__ __half g_W3h[EDIM * EDIM];
__device__ __half g_Wzh[EDIM * D1];

// ---------------- helpers ----------------
__device__ __forceinline__ uint32_t smem_u32(const void* p) {
    uint32_t a;
    asm("{ .reg .u64 t; cvta.to.shared.u64 t, %1; cvt.u32.u64 %0, t; }" : "=r"(a) : "l"(p));
    return a;
}

#define MMA_F16(ACC, AF, BF)                                                   \
    asm volatile(                                                              \
        "mma.sync.aligned.m16n8k16.row.col.f32.f16.f16.f32 "                   \
        "{%0,%1,%2,%3}, {%4,%5,%6,%7}, {%8,%9}, {%0,%1,%2,%3};"               \
        : "+f"((ACC)[0]), "+f"((ACC)[1]), "+f"((ACC)[2]), "+f"((ACC)[3])       \
        : "r"((AF)[0]), "r"((AF)[1]), "r"((AF)[2]), "r"((AF)[3]),              \
          "r"((BF)[0]), "r"((BF)[1]))

#define LDSM_X4(R0, R1, R2, R3, A)                                             \
    asm volatile("ldmatrix.sync.aligned.m8n8.x4.shared.b16 {%0,%1,%2,%3}, [%4];" \
        : "=r"(R0), "=r"(R1), "=r"(R2), "=r"(R3) : "r"(A))

#define LDSM_X4T(R0, R1, R2, R3, A)                                            \
    asm volatile("ldmatrix.sync.aligned.m8n8.x4.trans.shared.b16 {%0,%1,%2,%3}, [%4];" \
        : "=r"(R0), "=r"(R1), "=r"(R2), "=r"(R3) : "r"(A))

#define CP_ASYNC16(DST, SRC)                                                   \
    asm volatile("cp.async.cg.shared.global [%0], [%1], 16;" :: "r"(DST), "l"(SRC))
#define CP_COMMIT() asm volatile("cp.async.commit_group;" ::: "memory")
#define CP_WAIT1()  asm volatile("cp.async.wait_group 1;" ::: "memory")
#define CP_WAIT2()  asm volatile("cp.async.wait_group 2;" ::: "memory")

#define FFMA2(D, A, B, C)                                                      \
    asm("fma.rn.f32x2 %0, %1, %2, %3;" : "=l"(D) : "l"(A), "l"(B), "l"(C))

// ---------------- one-shot fp32->fp16 conversion of all 7 weights -----------
__global__ void f2h_all_kernel(const float* __restrict__ Wu, const float* __restrict__ Wv,
                               const float* __restrict__ Wo, const float* __restrict__ W1,
                               const float* __restrict__ W2, const float* __restrict__ W3,
                               const float* __restrict__ Wz,
                               __half* ou, __half* ov, __half* oo,
                               __half* o1, __half* o2, __half* o3, __half* oz) {
    int i = blockIdx.x * 256 + threadIdx.x;    // float4 index
    const float* src; __half* dst; int off;
    if      (i < 131072) { src = Wu; dst = ou; off = i; }
    else if (i < 262144) { src = Wv; dst = ov; off = i - 131072; }
    else if (i < 393216) { src = Wo; dst = oo; off = i - 262144; }
    else if (i < 458752) { src = W1; dst = o1; off = i - 393216; }
    else if (i < 524288) { src = W2; dst = o2; off = i - 458752; }
    else if (i < 589824) { src = W3; dst = o3; off = i - 524288; }
    else if (i < 720896) { src = Wz; dst = oz; off = i - 589824; }
    else return;
    float4 vv = *(const float4*)(src + off * 4);
    __half2 a = __floats2half2_rn(vv.x, vv.y);
    __half2 b = __floats2half2_rn(vv.z, vv.w);
    *(uint2*)(dst + off * 4) = make_uint2(*(uint32_t*)&a, *(uint32_t*)&b);
}

// ---------------- sRMS norm, dim = 512, fp16 out ----------------
__global__ void srms_kernel(const float* __restrict__ in, __half* __restrict__ out) {
    int row = blockIdx.x;
    const float4* ip = (const float4*)(in + (size_t)row * 512);
    int tid = threadIdx.x;                    // 0..127
    float4 val = ip[tid];
    float ss = val.x * val.x + val.y * val.y + val.z * val.z + val.w * val.w;
    #pragma unroll
    for (int o = 16; o > 0; o >>= 1) ss += __shfl_xor_sync(0xffffffffu, ss, o);
    __shared__ float wsum[4];
    if ((tid & 31) == 0) wsum[tid >> 5] = ss;
    __syncthreads();
    float tot = wsum[0] + wsum[1] + wsum[2] + wsum[3];
    float inv = 1.0f / (sqrtf(tot * (1.0f / 512.0f)) + 1e-8f);
    __half2 a = __floats2half2_rn(val.x * inv, val.y * inv);
    __half2 b = __floats2half2_rn(val.z * inv, val.w * inv);
    *(uint2*)(out + (size_t)row * 512 + tid * 4) = make_uint2(*(uint32_t*)&a, *(uint32_t*)&b);
}

// ---------------- fused coefficient MLP (4-stage cp.async) -------------------
#define CSTR 520                       // halfs per act/Bs row (512 + 8 pad)
#define CROWB (CSTR * 2)               // 1040 bytes
#define ACT_B (16 * CROWB)             // 16640
#define BSTG (32 * CROWB)              // 33280
#define COEF_STAGES 4
#define COEF_SMEM (2 * ACT_B + COEF_STAGES * BSTG + 1024)   // 167424

__device__ __forceinline__ void coef_load(const __half* __restrict__ Wg, int Nfull,
                                          int cOff, uint32_t bsBase, int st, int chunk,
                                          int tid) {
    if (chunk < 16) {
        uint32_t sb = bsBase + st * BSTG;
        int k0 = chunk * 32;
        #pragma unroll
        for (int j = 0; j < 8; j++) {
            int idx = j * 256 + tid;        // 0..2047
            int row = idx >> 6;             // 0..31
            int seg = idx & 63;             // 16B segments
            uint32_t dst = sb + row * CROWB + seg * 16;
            const __half* src = Wg + (size_t)(k0 + row) * Nfull + cOff + seg * 8;
            CP_ASYNC16(dst, src);
        }
    }
    CP_COMMIT();
}

__device__ __forceinline__ void coef_gemm(uint32_t actAddr, const __half* __restrict__ Wg,
                                          int Nfull, int cOff, uint32_t bsBase,
                                          float acc[8][4], int tid, int warp,
                                          int l16, int lh) {
    coef_load(Wg, Nfull, cOff, bsBase, 0, 0, tid);
    coef_load(Wg, Nfull, cOff, bsBase, 1, 1, tid);
    coef_load(Wg, Nfull, cOff, bsBase, 2, 2, tid);
    #pragma unroll 1
    for (int i = 0; i < 16; i++) {
        CP_WAIT2();
        __syncthreads();
        coef_load(Wg, Nfull, cOff, bsBase, (i + 3) % COEF_STAGES, i + 3, tid);
        uint32_t sB = bsBase + (i % COEF_STAGES) * BSTG;
        #pragma unroll
        for (int ks = 0; ks < 2; ks++) {
            uint32_t af[4];
            LDSM_X4(af[0], af[1], af[2], af[3],
                    actAddr + l16 * CROWB + i * 64 + ks * 32 + lh * 16);
            uint32_t bf[8][2];
            #pragma unroll
            for (int p = 0; p < 4; p++) {
                uint32_t baddr = sB + (ks * 16 + l16) * CROWB + warp * 128 + p * 32 + lh * 16;
                LDSM_X4T(bf[2 * p][0], bf[2 * p][1], bf[2 * p + 1][0], bf[2 * p + 1][1], baddr);
            }
            #pragma unroll
            for (int nt = 0; nt < 8; nt++) MMA_F16(acc[nt], af, bf[nt]);
        }
    }
}

__global__ void __launch_bounds__(256)
coef_mlp_kernel(const float* __restrict__ Wp, const float* __restrict__ bp,
                const __half* __restrict__ W1h, const float* __restrict__ b1,
                const __half* __restrict__ W2h, const float* __restrict__ b2,
                const __half* __restrict__ W3h, const float* __restrict__ b3,
                const __half* __restrict__ Wzh, const float* __restrict__ bz,
                float* __restrict__ arr) {
    extern __shared__ __align__(16) uint8_t sm[];
    __half* actA = (__half*)sm;
    __half* actB = (__half*)(sm + ACT_B);
    uint32_t bsBase = smem_u32(sm) + 2 * ACT_B;
    float* red = (float*)(sm + 2 * ACT_B + COEF_STAGES * BSTG);    // [16][8]

    int tid = threadIdx.x, warp = tid >> 5, lane = tid & 31;
    int l16 = lane & 15, lh = lane >> 4;
    int g = lane >> 2, t4 = lane & 3;
    int t0 = blockIdx.x * 16;
    float lg = logf(GAMMA_F);

    // ---- act0 = relu(srms(t*Wp + bp)) ----
    {
        int r = tid >> 4;                  // 0..15
        int c0 = (tid & 15) * 32;
        float tv = (float)(t0 + r);
        float vals[32];
        float ss = 0.0f;
        #pragma unroll
        for (int j = 0; j < 32; j++) {
            float hv = tv * Wp[c0 + j] + bp[c0 + j];
            vals[j] = hv;
            ss += hv * hv;
        }
        #pragma unroll
        for (int o = 8; o > 0; o >>= 1) ss += __shfl_xor_sync(0xffffffffu, ss, o);
        float inv = 1.0f / (sqrtf(ss * (1.0f / 512.0f)) + 1e-8f);
        __half* dst = actA + r * CSTR + c0;
        #pragma unroll
        for (int j = 0; j < 32; j += 2) {
            __half2 h = __floats2half2_rn(fmaxf(vals[j] * inv, 0.0f),
                                          fmaxf(vals[j + 1] * inv, 0.0f));
            *(uint32_t*)(dst + j) = *(uint32_t*)&h;
        }
    }
    __syncthreads();

    __half* cur = actA;
    __half* nxt = actB;

    // ---- three hidden layers ----
    #pragma unroll 1
    for (int layer = 0; layer < 3; layer++) {
        const __half* Wg = (layer == 0) ? W1h : (layer == 1) ? W2h : W3h;
        const float* bg  = (layer == 0) ? b1  : (layer == 1) ? b2  : b3;
        float acc[8][4];
        #pragma unroll
        for (int nt = 0; nt < 8; nt++)
            #pragma unroll
            for (int e = 0; e < 4; e++) acc[nt][e] = 0.0f;

        coef_gemm(smem_u32(cur), Wg, 512, 0, bsBase, acc, tid, warp, l16, lh);

        // epilogue: +bias, srms over 512 cols (cross-warp), relu, -> nxt (fp16)
        float ssA = 0.0f, ssB = 0.0f;
        #pragma unroll
        for (int nt = 0; nt < 8; nt++) {
            float2 bv = *(const float2*)(bg + warp * 64 + nt * 8 + 2 * t4);
            acc[nt][0] += bv.x; acc[nt][1] += bv.y;
            acc[nt][2] += bv.x; acc[nt][3] += bv.y;
            ssA += acc[nt][0] * acc[nt][0] + acc[nt][1] * acc[nt][1];
            ssB += acc[nt][2] * acc[nt][2] + acc[nt][3] * acc[nt][3];
        }
        ssA += __shfl_xor_sync(0xffffffffu, ssA, 1);
        ssA += __shfl_xor_sync(0xffffffffu, ssA, 2);
        ssB += __shfl_xor_sync(0xffffffffu, ssB, 1);
        ssB += __shfl_xor_sync(0xffffffffu, ssB, 2);
        __syncthreads();
        if (t4 == 0) {
            red[g * 8 + warp] = ssA;
            red[(g + 8) * 8 + warp] = ssB;
        }
        __syncthreads();
        float totA = 0.0f, totB = 0.0f;
        #pragma unroll
        for (int w2 = 0; w2 < 8; w2++) { totA += red[g * 8 + w2]; totB += red[(g + 8) * 8 + w2]; }
        float invA = 1.0f / (sqrtf(totA * (1.0f / 512.0f)) + 1e-8f);
        float invB = 1.0f / (sqrtf(totB * (1.0f / 512.0f)) + 1e-8f);
        #pragma unroll
        for (int nt = 0; nt < 8; nt++) {
            int col = warp * 64 + nt * 8 + 2 * t4;
            __half2 ha = __floats2half2_rn(fmaxf(acc[nt][0] * invA, 0.0f),
                                           fmaxf(acc[nt][1] * invA, 0.0f));
            __half2 hb = __floats2half2_rn(fmaxf(acc[nt][2] * invB, 0.0f),
                                           fmaxf(acc[nt][3] * invB, 0.0f));
            *(uint32_t*)(nxt + g * CSTR + col) = *(uint32_t*)&ha;
            *(uint32_t*)(nxt + (g + 8) * CSTR + col) = *(uint32_t*)&hb;
        }
        __syncthreads();
        __half* tmp = cur; cur = nxt; nxt = tmp;
    }

    // ---- final layer (Wz, N=1024): two 512-col passes + decay -> arr -------
    int rA = t0 + g, rB = t0 + g + 8;
    float decA = (rA == 0) ? 1.0f : expf((float)rA * lg);
    float decB = expf((float)rB * lg);
    #pragma unroll 1
    for (int nb = 0; nb < 2; nb++) {
        float acc[8][4];
        #pragma unroll
        for (int nt = 0; nt < 8; nt++)
            #pragma unroll
            for (int e = 0; e < 4; e++) acc[nt][e] = 0.0f;

        coef_gemm(smem_u32(cur), Wzh, 1024, nb * 512, bsBase, acc, tid, warp, l16, lh);

        #pragma unroll
        for (int nt = 0; nt < 8; nt++) {
            int col = nb * 512 + warp * 64 + nt * 8 + 2 * t4;
            float2 bv = *(const float2*)(bz + col);
            float2 oa = make_float2(decA * (acc[nt][0] + bv.x), decA * (acc[nt][1] + bv.y));
            float2 ob = make_float2(decB * (acc[nt][2] + bv.x), decB * (acc[nt][3] + bv.y));
            *(float2*)(arr + (size_t)rA * D1 + col) = oa;
            *(float2*)(arr + (size_t)rB * D1 + col) = ob;
        }
        __syncthreads();
    }
}

// ---------------- fp16 GEMM: cp.async 3-stage + ldmatrix, 128x128x32 ---------
// C[M,N] = A[M,K] @ W[K,N] + bias ; EPI: 1 silu, 3 +res
#define A_BYTES 10240               // 128*80
#define STAGE_B 18944               // A_BYTES + 32*272
#define G_STAGES 3
#define GEMM_SMEM (G_STAGES * STAGE_B)     // 56832

template <int EPI>
__device__ __forceinline__ void gemm_load_chunk(
    const __half* __restrict__ A, const __half* __restrict__ W,
    uint32_t sbase, int st, int i, int nch, int m0, int n0, int N, int K, int tid) {
    if (i < nch) {
        int k0 = i << 5;
        uint32_t sb = sbase + st * STAGE_B;
        #pragma unroll
        for (int j = 0; j < 2; j++) {
            int idx = j * 256 + tid;          // 0..511
            int rowa = idx >> 2;              // 0..127
            int sega = idx & 3;
            uint32_t dst = sb + rowa * 80 + sega * 16;
            const __half* src = A + (size_t)(m0 + rowa) * K + k0 + sega * 8;
            CP_ASYNC16(dst, src);
        }
        #pragma unroll
        for (int j = 0; j < 2; j++) {
            int idx = j * 256 + tid;
            int rowb = idx >> 4;              // 0..31
            int nseg = idx & 15;
            uint32_t dst = sb + A_BYTES + rowb * 272 + nseg * 16;
            const __half* src = W + (size_t)(k0 + rowb) * N + n0 + nseg * 8;
            CP_ASYNC16(dst, src);
        }
    }
    CP_COMMIT();
}

template <int EPI>
__global__ void __launch_bounds__(256)
hgemm_kernel(const __half* __restrict__ A, const __half* __restrict__ W,
             const float* __restrict__ bias, const float* __restrict__ res,
             float* __restrict__ C, int M, int N, int K) {
    extern __shared__ __align__(16) uint8_t smraw[];
    uint32_t sbase = smem_u32(smraw);

    int tid = threadIdx.x;             // 256
    int n0 = blockIdx.x * 128;
    int m0 = blockIdx.y * 128;
    int warp = tid >> 5, lane = tid & 31;
    int wm = warp >> 2;                // 0..1  (64-row slab)
    int wn = warp & 3;                 // 0..3  (32-col slab)
    int g = lane >> 2, t = lane & 3;
    int l16 = lane & 15, lh = lane >> 4;

    float acc[4][4][4];
    #pragma unroll
    for (int mt = 0; mt < 4; mt++)
        #pragma unroll
        for (int nt = 0; nt < 4; nt++)
            #pragma unroll
            for (int e = 0; e < 4; e++) acc[mt][nt][e] = 0.0f;

    int nch = K >> 5;
    gemm_load_chunk<EPI>(A, W, sbase, 0, 0, nch, m0, n0, N, K, tid);
    gemm_load_chunk<EPI>(A, W, sbase, 1, 1, nch, m0, n0, N, K, tid);

    #pragma unroll 1
    for (int i = 0; i < nch; i++) {
        CP_WAIT1();
        __syncthreads();
        gemm_load_chunk<EPI>(A, W, sbase, (i + 2) % G_STAGES, i + 2, nch, m0, n0, N, K, tid);

        int st = i % G_STAGES;
        uint32_t sA = sbase + st * STAGE_B;
        uint32_t sB = sA + A_BYTES;

        #pragma unroll
        for (int ks = 0; ks < 2; ks++) {
            uint32_t af[4][4], bf[4][2];
            #pragma unroll
            for (int mt = 0; mt < 4; mt++) {
                int row = wm * 64 + mt * 16 + l16;
                uint32_t addr = sA + row * 80 + (ks * 2 + lh) * 16;
                LDSM_X4(af[mt][0], af[mt][1], af[mt][2], af[mt][3], addr);
            }
            #pragma unroll
            for (int p = 0; p < 2; p++) {
                int rowb = ks * 16 + l16;
                int nseg = wn * 4 + p * 2 + lh;
                uint32_t addr = sB + rowb * 272 + nseg * 16;
                LDSM_X4T(bf[2 * p][0], bf[2 * p][1], bf[2 * p + 1][0], bf[2 * p + 1][1], addr);
            }
            #pragma unroll
            for (int mt = 0; mt < 4; mt++)
                #pragma unroll
                for (int nt = 0; nt < 4; nt++)
                    MMA_F16(acc[mt][nt], af[mt], bf[nt]);
        }
    }

    #pragma unroll
    for (int mt = 0; mt < 4; mt++) {
        int mrow0 = m0 + wm * 64 + mt * 16 + g;
        #pragma unroll
        for (int h2 = 0; h2 < 2; h2++) {
            int m = mrow0 + 8 * h2;
            #pragma unroll
            for (int nt = 0; nt < 4; nt++) {
                int n = n0 + wn * 32 + nt * 8 + 2 * t;
                float v0 = acc[mt][nt][2 * h2 + 0] + bias[n];
                float v1 = acc[mt][nt][2 * h2 + 1] + bias[n + 1];
                if (EPI == 1) {
                    v0 = v0 / (1.0f + expf(-v0));
                    v1 = v1 / (1.0f + expf(-v1));
                }
                if (EPI == 3) {
                    float2 rv = *(const float2*)(res + (size_t)m * N + n);
                    v0 += rv.x; v1 += rv.y;
                }
                *(float2*)(C + (size_t)m * N + n) = make_float2(v0, v1);
            }
        }
    }
}

// ---------------- causal depthwise Toeplitz conv + gate ----------------------
// Circular 256-row v window; one batch per launch (grid 16 x 16).
#define CONV_SMEM ((64 * 64 + 256 * 64) * 4)   // 81920

__global__ void __launch_bounds__(256)
conv_kernel(const float* __restrict__ v, const float* __restrict__ arr,
            const float* __restrict__ u, __half* __restrict__ yh, int b) {
    extern __shared__ float cs[];
    float* a_s = cs;              // [64][64]
    float* v_s = cs + 64 * 64;    // [256][64] circular by global row & 255

    int c0 = blockIdx.y * 64;
    int iblk = (gridDim.x - 1) - blockIdx.x;   // heaviest tiles first
    int t0 = iblk * 128;
    int tid = threadIdx.x;                     // 256
    int tx = tid & 15;                         // c group (4 channels)
    int ty = tid >> 4;                         // t group (8 rows)

    unsigned long long acc2[8][2];
    #pragma unroll
    for (int i = 0; i < 8; i++) { acc2[i][0] = 0ULL; acc2[i][1] = 0ULL; }

    const float* vb = v + (size_t)b * NTOK * D1;
    int nch = 2 * iblk + 2;

    for (int jb = 0; jb < nch; jb++) {
        __syncthreads();
        // a chunk: rows jb*64..+63, cols c0..c0+63
        #pragma unroll
        for (int it = 0; it < 4; it++) {
            int idx = it * 256 + tid;
            int rq = idx >> 4;
            int cseg = idx & 15;
            float4 val = *(const float4*)(arr + (size_t)(jb * 64 + rq) * D1 + c0 + cseg * 4);
            *(float4*)(&a_s[rq * 64 + cseg * 4]) = val;
        }
        // v rows: window low = t0 - jb*64 - 63; load 64 new rows (192 if jb==0)
        int wlo = t0 - jb * 64 - 63;
        int ngrp = (jb == 0) ? 3 : 1;
        for (int grp = 0; grp < ngrp; grp++) {
            #pragma unroll
            for (int it = 0; it < 4; it++) {
                int idx = it * 256 + tid;      // 0..1023
                int rl = idx >> 4;             // 0..63
                int cseg = idx & 15;
                int gg = wlo + grp * 64 + rl;
                int slot = (gg + 1024) & 255;
                float4 val = make_float4(0.0f, 0.0f, 0.0f, 0.0f);
                if (gg >= 0 && gg < NTOK)
                    val = *(const float4*)(vb + (size_t)gg * D1 + c0 + cseg * 4);
                *(float4*)(&v_s[slot * 64 + cseg * 4]) = val;
            }
        }
        __syncthreads();

        // register sliding window; global row base for q=0
        int base = t0 - jb * 64 + 1024 + ty * 8;
        unsigned long long w2[8][2];
        #pragma unroll
        for (int i = 0; i < 8; i++) {
            int slot = (base + i) & 255;
            ulonglong2 wv = *(const ulonglong2*)(&v_s[slot * 64 + tx * 4]);
            w2[i][0] = wv.x; w2[i][1] = wv.y;
        }

        #pragma unroll 8
        for (int q = 0; q < 64; q++) {
            ulonglong2 a2 = *(const ulonglong2*)(&a_s[q * 64 + tx * 4]);
            #pragma unroll
            for (int i = 0; i < 8; i++) {
                FFMA2(acc2[i][0], a2.x, w2[i][0], acc2[i][0]);
                FFMA2(acc2[i][1], a2.y, w2[i][1], acc2[i][1]);
            }
            if (q < 63) {
                #pragma unroll
                for (int i = 7; i > 0; i--) { w2[i][0] = w2[i - 1][0]; w2[i][1] = w2[i - 1][1]; }
                int slot = (base - 1 - q) & 255;
                ulonglong2 wv = *(const ulonglong2*)(&v_s[slot * 64 + tx * 4]);
                w2[0][0] = wv.x; w2[0][1] = wv.y;
            }
        }
    }

    #pragma unroll
    for (int i = 0; i < 8; i++) {
        int t = t0 + ty * 8 + i;
        size_t off = ((size_t)b * NTOK + t) * D1 + c0 + tx * 4;
        float4 uv = *(const float4*)(u + off);
        float2 lo = *(float2*)(&acc2[i][0]);
        float2 hi = *(float2*)(&acc2[i][1]);
        __half2 ha = __floats2half2_rn(uv.x * lo.x, uv.y * lo.y);
        __half2 hb = __floats2half2_rn(uv.z * hi.x, uv.w * hi.y);
        *(uint2*)(yh + off) = make_uint2(*(uint32_t*)&ha, *(uint32_t*)&hb);
    }
}

// ---------------- launch ----------------
extern "C" void kernel_launch(void* const* d_in, const int* in_sizes, int n_in,
                              void* d_out, int out_size) {
    const float* x  = (const float*)d_in[0];
    const float* Wu = (const float*)d_in[1];
    const float* bu = (const float*)d_in[2];
    const float* Wv = (const float*)d_in[3];
    const float* bv = (const float*)d_in[4];
    const float* Wo = (const float*)d_in[5];
    const float* bo = (const float*)d_in[6];
    const float* Wp = (const float*)d_in[7];
    const float* bp = (const float*)d_in[8];
    const float* W1 = (const float*)d_in[9];
    const float* b1 = (const float*)d_in[10];
    const float* W2 = (const float*)d_in[11];
    const float* b2 = (const float*)d_in[12];
    const float* W3 = (const float*)d_in[13];
    const float* b3 = (const float*)d_in[14];
    const float* Wz = (const float*)d_in[15];
    const float* bz = (const float*)d_in[16];
    float* out = (float*)d_out;

    float *u, *v, *arr;
    __half *xnh, *yh, *Wuh, *Wvh, *Woh, *W1h, *W2h, *W3h, *Wzh;
    cudaGetSymbolAddress((void**)&u,    g_u);
    cudaGetSymbolAddress((void**)&v,    g_v);
    cudaGetSymbolAddress((void**)&arr,  g_arr);
    cudaGetSymbolAddress((void**)&xnh,  g_xnh);
    cudaGetSymbolAddress((void**)&yh,   g_yh);
    cudaGetSymbolAddress((void**)&Wuh,  g_Wuh);
    cudaGetSymbolAddress((void**)&Wvh,  g_Wvh);
    cudaGetSymbolAddress((void**)&Woh,  g_Woh);
    cudaGetSymbolAddress((void**)&W1h,  g_W1h);
    cudaGetSymbolAddress((void**)&W2h,  g_W2h);
    cudaGetSymbolAddress((void**)&W3h,  g_W3h);
    cudaGetSymbolAddress((void**)&Wzh,  g_Wzh);

    cudaFuncSetAttribute(hgemm_kernel<1>, cudaFuncAttributeMaxDynamicSharedMemorySize, GEMM_SMEM);
    cudaFuncSetAttribute(hgemm_kernel<3>, cudaFuncAttributeMaxDynamicSharedMemorySize, GEMM_SMEM);
    cudaFuncSetAttribute(conv_kernel,     cudaFuncAttributeMaxDynamicSharedMemorySize, CONV_SMEM);
    cudaFuncSetAttribute(coef_mlp_kernel, cudaFuncAttributeMaxDynamicSharedMemorySize, COEF_SMEM);

    // forked streams + events (graph-capturable cross-stream dependencies)
    cudaStream_t s1, s2;
    cudaStreamCreateWithFlags(&s1, cudaStreamNonBlocking);
    cudaStreamCreateWithFlags(&s2, cudaStreamNonBlocking);
    cudaEvent_t evF, evC, evConv[NB], evD;
    cudaEventCreateWithFlags(&evF, cudaEventDisableTiming);
    cudaEventCreateWithFlags(&evC, cudaEventDisableTiming);
    for (int b = 0; b < NB; b++) cudaEventCreateWithFlags(&evConv[b], cudaEventDisableTiming);
    cudaEventCreateWithFlags(&evD, cudaEventDisableTiming);

    // s0: weight conversion, then main-path norm
    f2h_all_kernel<<<2816, 256>>>(Wu, Wv, Wo, W1, W2, W3, Wz,
                                  Wuh, Wvh, Woh, W1h, W2h, W3h, Wzh);
    cudaEventRecord(evF, 0);
    srms_kernel<<<ROWS, 128>>>(x, xnh);

    // s1: coefficient MLP (needs weights only) runs concurrent with u/v gemms
    cudaStreamWaitEvent(s1, evF, 0);
    coef_mlp_kernel<<<NTOK / 16, 256, COEF_SMEM, s1>>>(Wp, bp, W1h, b1, W2h, b2,
                                                       W3h, b3, Wzh, bz, arr);
    cudaEventRecord(evC, s1);

    // s0: u, v projections with SiLU
    hgemm_kernel<1><<<dim3(D1 / 128, ROWS / 128), 256, GEMM_SMEM>>>(xnh, Wuh, bu, nullptr, u, ROWS, D1, DDIM);
    hgemm_kernel<1><<<dim3(D1 / 128, ROWS / 128), 256, GEMM_SMEM>>>(xnh, Wvh, bv, nullptr, v, ROWS, D1, DDIM);

    // s0 waits for coef; then per-batch conv, each followed by outproj on s2
    cudaStreamWaitEvent(0, evC, 0);
    for (int b = 0; b < NB; b++) {
        conv_kernel<<<dim3(NTOK / 128, D1 / 64), 256, CONV_SMEM>>>(v, arr, u, yh, b);
        cudaEventRecord(evConv[b], 0);
        cudaStreamWaitEvent(s2, evConv[b], 0);
        hgemm_kernel<3><<<dim3(DDIM / 128, NTOK / 128), 256, GEMM_SMEM, s2>>>(
            yh + (size_t)b * NTOK * D1, Woh, bo,
            x + (size_t)b * NTOK * DDIM,
            out + (size_t)b * NTOK * DDIM, NTOK, DDIM, D1);
    }
    cudaEventRecord(evD, s2);
    cudaStreamWaitEvent(0, evD, 0);   // rejoin before capture ends

    cudaStreamDestroy(s1);
    cudaStreamDestroy(s2);
    cudaEventDestroy(evF);
    cudaEventDestroy(evC);
    for (int b = 0; b < NB; b++) cudaEventDestroy(evConv[b]);
    cudaEventDestroy(evD);
}

// round 17
// speedup vs baseline: 1.6192x; 1.6192x over previous
#include <cuda_runtime.h>
#include <cuda_fp16.h>
#include <math.h>
#include <stdint.h>

#define NTOK 2048
#define NB 4
#define DDIM 512
#define D1 1024
#define EDIM 512
#define ROWS (NB * NTOK)   // 8192
#define GAMMA_F 0.999f

// ---------------- scratch (device globals: allocation-free) ----------------
__device__ float  g_u  [ROWS * D1];
__device__ float  g_v  [ROWS * D1];
__device__ float  g_arr[NTOK * D1];
__device__ __half g_xnh [ROWS * DDIM];
__device__ __half g_yh  [ROWS * D1];
__device__ __half g_Wuh[DDIM * D1];
__device__ __half g_Wvh[DDIM * D1];
__device__ __half g_Woh[D1 * DDIM];
__device__ __half g_W1h[EDIM * EDIM];
__device__ __half g_W2h[EDIM * EDIM];
__device__ __half g_W3h[EDIM * EDIM];
__device__ __half g_Wzh[EDIM * D1];

// ---------------- helpers ----------------
__device__ __forceinline__ uint32_t smem_u32(const void* p) {
    uint32_t a;
    asm("{ .reg .u64 t; cvta.to.shared.u64 t, %1; cvt.u32.u64 %0, t; }" : "=r"(a) : "l"(p));
    return a;
}

#define MMA_F16(ACC, AF, BF)                                                   \
    asm volatile(                                                              \
        "mma.sync.aligned.m16n8k16.row.col.f32.f16.f16.f32 "                   \
        "{%0,%1,%2,%3}, {%4,%5,%6,%7}, {%8,%9}, {%0,%1,%2,%3};"               \
        : "+f"((ACC)[0]), "+f"((ACC)[1]), "+f"((ACC)[2]), "+f"((ACC)[3])       \
        : "r"((AF)[0]), "r"((AF)[1]), "r"((AF)[2]), "r"((AF)[3]),              \
          "r"((BF)[0]), "r"((BF)[1]))

#define LDSM_X4(R0, R1, R2, R3, A)                                             \
    asm volatile("ldmatrix.sync.aligned.m8n8.x4.shared.b16 {%0,%1,%2,%3}, [%4];" \
        : "=r"(R0), "=r"(R1), "=r"(R2), "=r"(R3) : "r"(A))

#define LDSM_X4T(R0, R1, R2, R3, A)                                            \
    asm volatile("ldmatrix.sync.aligned.m8n8.x4.trans.shared.b16 {%0,%1,%2,%3}, [%4];" \
        : "=r"(R0), "=r"(R1), "=r"(R2), "=r"(R3) : "r"(A))

#define CP_ASYNC16(DST, SRC)                                                   \
    asm volatile("cp.async.cg.shared.global [%0], [%1], 16;" :: "r"(DST), "l"(SRC))
#define CP_COMMIT() asm volatile("cp.async.commit_group;" ::: "memory")
#define CP_WAIT1()  asm volatile("cp.async.wait_group 1;" ::: "memory")
#define CP_WAIT2()  asm volatile("cp.async.wait_group 2;" ::: "memory")

#define FFMA2(D, A, B, C)                                                      \
    asm("fma.rn.f32x2 %0, %1, %2, %3;" : "=l"(D) : "l"(A), "l"(B), "l"(C))

// ---------------- one-shot fp32->fp16 conversion of all 7 weights -----------
__global__ void f2h_all_kernel(const float* __restrict__ Wu, const float* __restrict__ Wv,
                               const float* __restrict__ Wo, const float* __restrict__ W1,
                               const float* __restrict__ W2, const float* __restrict__ W3,
                               const float* __restrict__ Wz,
                               __half* ou, __half* ov, __half* oo,
                               __half* o1, __half* o2, __half* o3, __half* oz) {
    int i = blockIdx.x * 256 + threadIdx.x;    // float4 index
    const float* src; __half* dst; int off;
    if      (i < 131072) { src = Wu; dst = ou; off = i; }
    else if (i < 262144) { src = Wv; dst = ov; off = i - 131072; }
    else if (i < 393216) { src = Wo; dst = oo; off = i - 262144; }
    else if (i < 458752) { src = W1; dst = o1; off = i - 393216; }
    else if (i < 524288) { src = W2; dst = o2; off = i - 458752; }
    else if (i < 589824) { src = W3; dst = o3; off = i - 524288; }
    else if (i < 720896) { src = Wz; dst = oz; off = i - 589824; }
    else return;
    float4 vv = *(const float4*)(src + off * 4);
    __half2 a = __floats2half2_rn(vv.x, vv.y);
    __half2 b = __floats2half2_rn(vv.z, vv.w);
    *(uint2*)(dst + off * 4) = make_uint2(*(uint32_t*)&a, *(uint32_t*)&b);
}

// ---------------- sRMS norm, dim = 512, fp16 out ----------------
__global__ void srms_kernel(const float* __restrict__ in, __half* __restrict__ out) {
    int row = blockIdx.x;
    const float4* ip = (const float4*)(in + (size_t)row * 512);
    int tid = threadIdx.x;                    // 0..127
    float4 val = ip[tid];
    float ss = val.x * val.x + val.y * val.y + val.z * val.z + val.w * val.w;
    #pragma unroll
    for (int o = 16; o > 0; o >>= 1) ss += __shfl_xor_sync(0xffffffffu, ss, o);
    __shared__ float wsum[4];
    if ((tid & 31) == 0) wsum[tid >> 5] = ss;
    __syncthreads();
    float tot = wsum[0] + wsum[1] + wsum[2] + wsum[3];
    float inv = 1.0f / (sqrtf(tot * (1.0f / 512.0f)) + 1e-8f);
    __half2 a = __floats2half2_rn(val.x * inv, val.y * inv);
    __half2 b = __floats2half2_rn(val.z * inv, val.w * inv);
    *(uint2*)(out + (size_t)row * 512 + tid * 4) = make_uint2(*(uint32_t*)&a, *(uint32_t*)&b);
}

// ---------------- fused coefficient MLP (4-stage cp.async) -------------------
#define CSTR 520                       // halfs per act/Bs row (512 + 8 pad)
#define CROWB (CSTR * 2)               // 1040 bytes
#define ACT_B (16 * CROWB)             // 16640
#define BSTG (32 * CROWB)              // 33280
#define COEF_STAGES 4
#define COEF_SMEM (2 * ACT_B + COEF_STAGES * BSTG + 1024)   // 167424

__device__ __forceinline__ void coef_load(const __half* __restrict__ Wg, int Nfull,
                                          int cOff, uint32_t bsBase, int st, int chunk,
                                          int tid) {
    if (chunk < 16) {
        uint32_t sb = bsBase + st * BSTG;
        int k0 = chunk * 32;
        #pragma unroll
        for (int j = 0; j < 8; j++) {
            int idx = j * 256 + tid;        // 0..2047
            int row = idx >> 6;             // 0..31
            int seg = idx & 63;             // 16B segments
            uint32_t dst = sb + row * CROWB + seg * 16;
            const __half* src = Wg + (size_t)(k0 + row) * Nfull + cOff + seg * 8;
            CP_ASYNC16(dst, src);
        }
    }
    CP_COMMIT();
}

__device__ __forceinline__ void coef_gemm(uint32_t actAddr, const __half* __restrict__ Wg,
                                          int Nfull, int cOff, uint32_t bsBase,
                                          float acc[8][4], int tid, int warp,
                                          int l16, int lh) {
    coef_load(Wg, Nfull, cOff, bsBase, 0, 0, tid);
    coef_load(Wg, Nfull, cOff, bsBase, 1, 1, tid);
    coef_load(Wg, Nfull, cOff, bsBase, 2, 2, tid);
    #pragma unroll 1
    for (int i = 0; i < 16; i++) {
        CP_WAIT2();
        __syncthreads();
        coef_load(Wg, Nfull, cOff, bsBase, (i + 3) % COEF_STAGES, i + 3, tid);
        uint32_t sB = bsBase + (i % COEF_STAGES) * BSTG;
        #pragma unroll
        for (int ks = 0; ks < 2; ks++) {
            uint32_t af[4];
            LDSM_X4(af[0], af[1], af[2], af[3],
                    actAddr + l16 * CROWB + i * 64 + ks * 32 + lh * 16);
            uint32_t bf[8][2];
            #pragma unroll
            for (int p = 0; p < 4; p++) {
                uint32_t baddr = sB + (ks * 16 + l16) * CROWB + warp * 128 + p * 32 + lh * 16;
                LDSM_X4T(bf[2 * p][0], bf[2 * p][1], bf[2 * p + 1][0], bf[2 * p + 1][1], baddr);
            }
            #pragma unroll
            for (int nt = 0; nt < 8; nt++) MMA_F16(acc[nt], af, bf[nt]);
        }
    }
}

__global__ void __launch_bounds__(256)
coef_mlp_kernel(const float* __restrict__ Wp, const float* __restrict__ bp,
                const __half* __restrict__ W1h, const float* __restrict__ b1,
                const __half* __restrict__ W2h, const float* __restrict__ b2,
                const __half* __restrict__ W3h, const float* __restrict__ b3,
                const __half* __restrict__ Wzh, const float* __restrict__ bz,
                float* __restrict__ arr) {
    extern __shared__ __align__(16) uint8_t sm[];
    __half* actA = (__half*)sm;
    __half* actB = (__half*)(sm + ACT_B);
    uint32_t bsBase = smem_u32(sm) + 2 * ACT_B;
    float* red = (float*)(sm + 2 * ACT_B + COEF_STAGES * BSTG);    // [16][8]

    int tid = threadIdx.x, warp = tid >> 5, lane = tid & 31;
    int l16 = lane & 15, lh = lane >> 4;
    int g = lane >> 2, t4 = lane & 3;
    int t0 = blockIdx.x * 16;
    float lg = logf(GAMMA_F);

    // ---- act0 = relu(srms(t*Wp + bp)) ----
    {
        int r = tid >> 4;                  // 0..15
        int c0 = (tid & 15) * 32;
        float tv = (float)(t0 + r);
        float vals[32];
        float ss = 0.0f;
        #pragma unroll
        for (int j = 0; j < 32; j++) {
            float hv = tv * Wp[c0 + j] + bp[c0 + j];
            vals[j] = hv;
            ss += hv * hv;
        }
        #pragma unroll
        for (int o = 8; o > 0; o >>= 1) ss += __shfl_xor_sync(0xffffffffu, ss, o);
        float inv = 1.0f / (sqrtf(ss * (1.0f / 512.0f)) + 1e-8f);
        __half* dst = actA + r * CSTR + c0;
        #pragma unroll
        for (int j = 0; j < 32; j += 2) {
            __half2 h = __floats2half2_rn(fmaxf(vals[j] * inv, 0.0f),
                                          fmaxf(vals[j + 1] * inv, 0.0f));
            *(uint32_t*)(dst + j) = *(uint32_t*)&h;
        }
    }
    __syncthreads();

    __half* cur = actA;
    __half* nxt = actB;

    // ---- three hidden layers ----
    #pragma unroll 1
    for (int layer = 0; layer < 3; layer++) {
        const __half* Wg = (layer == 0) ? W1h : (layer == 1) ? W2h : W3h;
        const float* bg  = (layer == 0) ? b1  : (layer == 1) ? b2  : b3;
        float acc[8][4];
        #pragma unroll
        for (int nt = 0; nt < 8; nt++)
            #pragma unroll
            for (int e = 0; e < 4; e++) acc[nt][e] = 0.0f;

        coef_gemm(smem_u32(cur), Wg, 512, 0, bsBase, acc, tid, warp, l16, lh);

        // epilogue: +bias, srms over 512 cols (cross-warp), relu, -> nxt (fp16)
        float ssA = 0.0f, ssB = 0.0f;
        #pragma unroll
        for (int nt = 0; nt < 8; nt++) {
            float2 bv = *(const float2*)(bg + warp * 64 + nt * 8 + 2 * t4);
            acc[nt][0] += bv.x; acc[nt][1] += bv.y;
            acc[nt][2] += bv.x; acc[nt][3] += bv.y;
            ssA += acc[nt][0] * acc[nt][0] + acc[nt][1] * acc[nt][1];
            ssB += acc[nt][2] * acc[nt][2] + acc[nt][3] * acc[nt][3];
        }
        ssA += __shfl_xor_sync(0xffffffffu, ssA, 1);
        ssA += __shfl_xor_sync(0xffffffffu, ssA, 2);
        ssB += __shfl_xor_sync(0xffffffffu, ssB, 1);
        ssB += __shfl_xor_sync(0xffffffffu, ssB, 2);
        __syncthreads();
        if (t4 == 0) {
            red[g * 8 + warp] = ssA;
            red[(g + 8) * 8 + warp] = ssB;
        }
        __syncthreads();
        float totA = 0.0f, totB = 0.0f;
        #pragma unroll
        for (int w2 = 0; w2 < 8; w2++) { totA += red[g * 8 + w2]; totB += red[(g + 8) * 8 + w2]; }
        float invA = 1.0f / (sqrtf(totA * (1.0f / 512.0f)) + 1e-8f);
        float invB = 1.0f / (sqrtf(totB * (1.0f / 512.0f)) + 1e-8f);
        #pragma unroll
        for (int nt = 0; nt < 8; nt++) {
            int col = warp * 64 + nt * 8 + 2 * t4;
            __half2 ha = __floats2half2_rn(fmaxf(acc[nt][0] * invA, 0.0f),
                                           fmaxf(acc[nt][1] * invA, 0.0f));
            __half2 hb = __floats2half2_rn(fmaxf(acc[nt][2] * invB, 0.0f),
                                           fmaxf(acc[nt][3] * invB, 0.0f));
            *(uint32_t*)(nxt + g * CSTR + col) = *(uint32_t*)&ha;
            *(uint32_t*)(nxt + (g + 8) * CSTR + col) = *(uint32_t*)&hb;
        }
        __syncthreads();
        __half* tmp = cur; cur = nxt; nxt = tmp;
    }

    // ---- final layer (Wz, N=1024): two 512-col passes + decay -> arr -------
    int rA = t0 + g, rB = t0 + g + 8;
    float decA = (rA == 0) ? 1.0f : expf((float)rA * lg);
    float decB = expf((float)rB * lg);
    #pragma unroll 1
    for (int nb = 0; nb < 2; nb++) {
        float acc[8][4];
        #pragma unroll
        for (int nt = 0; nt < 8; nt++)
            #pragma unroll
            for (int e = 0; e < 4; e++) acc[nt][e] = 0.0f;

        coef_gemm(smem_u32(cur), Wzh, 1024, nb * 512, bsBase, acc, tid, warp, l16, lh);

        #pragma unroll
        for (int nt = 0; nt < 8; nt++) {
            int col = nb * 512 + warp * 64 + nt * 8 + 2 * t4;
            float2 bv = *(const float2*)(bz + col);
            float2 oa = make_float2(decA * (acc[nt][0] + bv.x), decA * (acc[nt][1] + bv.y));
            float2 ob = make_float2(decB * (acc[nt][2] + bv.x), decB * (acc[nt][3] + bv.y));
            *(float2*)(arr + (size_t)rA * D1 + col) = oa;
            *(float2*)(arr + (size_t)rB * D1 + col) = ob;
        }
        __syncthreads();
    }
}

// ---------------- fp16 GEMM: cp.async 3-stage + ldmatrix, 128x128x32 ---------
// C[M,N] = A[M,K] @ W[K,N] + bias ; EPI: 1 silu, 3 +res
#define A_BYTES 10240               // 128*80
#define STAGE_B 18944               // A_BYTES + 32*272
#define G_STAGES 3
#define GEMM_SMEM (G_STAGES * STAGE_B)     // 56832

template <int EPI>
__device__ __forceinline__ void gemm_load_chunk(
    const __half* __restrict__ A, const __half* __restrict__ W,
    uint32_t sbase, int st, int i, int nch, int m0, int n0, int N, int K, int tid) {
    if (i < nch) {
        int k0 = i << 5;
        uint32_t sb = sbase + st * STAGE_B;
        #pragma unroll
        for (int j = 0; j < 2; j++) {
            int idx = j * 256 + tid;          // 0..511
            int rowa = idx >> 2;              // 0..127
            int sega = idx & 3;
            uint32_t dst = sb + rowa * 80 + sega * 16;
            const __half* src = A + (size_t)(m0 + rowa) * K + k0 + sega * 8;
            CP_ASYNC16(dst, src);
        }
        #pragma unroll
        for (int j = 0; j < 2; j++) {
            int idx = j * 256 + tid;
            int rowb = idx >> 4;              // 0..31
            int nseg = idx & 15;
            uint32_t dst = sb + A_BYTES + rowb * 272 + nseg * 16;
            const __half* src = W + (size_t)(k0 + rowb) * N + n0 + nseg * 8;
            CP_ASYNC16(dst, src);
        }
    }
    CP_COMMIT();
}

template <int EPI>
__global__ void __launch_bounds__(256)
hgemm_kernel(const __half* __restrict__ A, const __half* __restrict__ W,
             const float* __restrict__ bias, const float* __restrict__ res,
             float* __restrict__ C, int M, int N, int K) {
    extern __shared__ __align__(16) uint8_t smraw[];
    uint32_t sbase = smem_u32(smraw);

    int tid = threadIdx.x;             // 256
    int n0 = blockIdx.x * 128;
    int m0 = blockIdx.y * 128;
    int warp = tid >> 5, lane = tid & 31;
    int wm = warp >> 2;                // 0..1  (64-row slab)
    int wn = warp & 3;                 // 0..3  (32-col slab)
    int g = lane >> 2, t = lane & 3;
    int l16 = lane & 15, lh = lane >> 4;

    float acc[4][4][4];
    #pragma unroll
    for (int mt = 0; mt < 4; mt++)
        #pragma unroll
        for (int nt = 0; nt < 4; nt++)
            #pragma unroll
            for (int e = 0; e < 4; e++) acc[mt][nt][e] = 0.0f;

    int nch = K >> 5;
    gemm_load_chunk<EPI>(A, W, sbase, 0, 0, nch, m0, n0, N, K, tid);
    gemm_load_chunk<EPI>(A, W, sbase, 1, 1, nch, m0, n0, N, K, tid);

    #pragma unroll 1
    for (int i = 0; i < nch; i++) {
        CP_WAIT1();
        __syncthreads();
        gemm_load_chunk<EPI>(A, W, sbase, (i + 2) % G_STAGES, i + 2, nch, m0, n0, N, K, tid);

        int st = i % G_STAGES;
        uint32_t sA = sbase + st * STAGE_B;
        uint32_t sB = sA + A_BYTES;

        #pragma unroll
        for (int ks = 0; ks < 2; ks++) {
            uint32_t af[4][4], bf[4][2];
            #pragma unroll
            for (int mt = 0; mt < 4; mt++) {
                int row = wm * 64 + mt * 16 + l16;
                uint32_t addr = sA + row * 80 + (ks * 2 + lh) * 16;
                LDSM_X4(af[mt][0], af[mt][1], af[mt][2], af[mt][3], addr);
            }
            #pragma unroll
            for (int p = 0; p < 2; p++) {
                int rowb = ks * 16 + l16;
                int nseg = wn * 4 + p * 2 + lh;
                uint32_t addr = sB + rowb * 272 + nseg * 16;
                LDSM_X4T(bf[2 * p][0], bf[2 * p][1], bf[2 * p + 1][0], bf[2 * p + 1][1], addr);
            }
            #pragma unroll
            for (int mt = 0; mt < 4; mt++)
                #pragma unroll
                for (int nt = 0; nt < 4; nt++)
                    MMA_F16(acc[mt][nt], af[mt], bf[nt]);
        }
    }

    #pragma unroll
    for (int mt = 0; mt < 4; mt++) {
        int mrow0 = m0 + wm * 64 + mt * 16 + g;
        #pragma unroll
        for (int h2 = 0; h2 < 2; h2++) {
            int m = mrow0 + 8 * h2;
            #pragma unroll
            for (int nt = 0; nt < 4; nt++) {
                int n = n0 + wn * 32 + nt * 8 + 2 * t;
                float v0 = acc[mt][nt][2 * h2 + 0] + bias[n];
                float v1 = acc[mt][nt][2 * h2 + 1] + bias[n + 1];
                if (EPI == 1) {
                    v0 = v0 / (1.0f + expf(-v0));
                    v1 = v1 / (1.0f + expf(-v1));
                }
                if (EPI == 3) {
                    float2 rv = *(const float2*)(res + (size_t)m * N + n);
                    v0 += rv.x; v1 += rv.y;
                }
                *(float2*)(C + (size_t)m * N + n) = make_float2(v0, v1);
            }
        }
    }
}

// ---------------- causal depthwise Toeplitz conv + gate ----------------------
// Circular 256-row v window: only 64 new rows loaded per chunk (192 on first).
#define CONV_SMEM ((64 * 64 + 256 * 64) * 4)   // 81920

__global__ void __launch_bounds__(256)
conv_kernel(const float* __restrict__ v, const float* __restrict__ arr,
            const float* __restrict__ u, __half* __restrict__ yh) {
    extern __shared__ float cs[];
    float* a_s = cs;              // [64][64]
    float* v_s = cs + 64 * 64;    // [256][64] circular by global row & 255

    int b = blockIdx.z;
    int c0 = blockIdx.y * 64;
    int iblk = (gridDim.x - 1) - blockIdx.x;   // heaviest tiles first
    int t0 = iblk * 128;
    int tid = threadIdx.x;                     // 256
    int tx = tid & 15;                         // c group (4 channels)
    int ty = tid >> 4;                         // t group (8 rows)

    unsigned long long acc2[8][2];
    #pragma unroll
    for (int i = 0; i < 8; i++) { acc2[i][0] = 0ULL; acc2[i][1] = 0ULL; }

    const float* vb = v + (size_t)b * NTOK * D1;
    int nch = 2 * iblk + 2;

    for (int jb = 0; jb < nch; jb++) {
        __syncthreads();
        // a chunk: rows jb*64..+63, cols c0..c0+63
        #pragma unroll
        for (int it = 0; it < 4; it++) {
            int idx = it * 256 + tid;
            int rq = idx >> 4;
            int cseg = idx & 15;
            float4 val = *(const float4*)(arr + (size_t)(jb * 64 + rq) * D1 + c0 + cseg * 4);
            *(float4*)(&a_s[rq * 64 + cseg * 4]) = val;
        }
        // v rows: window low = t0 - jb*64 - 63; load 64 new rows (192 if jb==0)
        int wlo = t0 - jb * 64 - 63;
        int ngrp = (jb == 0) ? 3 : 1;
        for (int grp = 0; grp < ngrp; grp++) {
            #pragma unroll
            for (int it = 0; it < 4; it++) {
                int idx = it * 256 + tid;      // 0..1023
                int rl = idx >> 4;             // 0..63
                int cseg = idx & 15;
                int gg = wlo + grp * 64 + rl;
                int slot = (gg + 1024) & 255;
                float4 val = make_float4(0.0f, 0.0f, 0.0f, 0.0f);
                if (gg >= 0 && gg < NTOK)
                    val = *(const float4*)(vb + (size_t)gg * D1 + c0 + cseg * 4);
                *(float4*)(&v_s[slot * 64 + cseg * 4]) = val;
            }
        }
        __syncthreads();

        // register sliding window; global row base for q=0
        int base = t0 - jb * 64 + 1024 + ty * 8;
        unsigned long long w2[8][2];
        #pragma unroll
        for (int i = 0; i < 8; i++) {
            int slot = (base + i) & 255;
            ulonglong2 wv = *(const ulonglong2*)(&v_s[slot * 64 + tx * 4]);
            w2[i][0] = wv.x; w2[i][1] = wv.y;
        }

        #pragma unroll 8
        for (int q = 0; q < 64; q++) {
            ulonglong2 a2 = *(const ulonglong2*)(&a_s[q * 64 + tx * 4]);
            #pragma unroll
            for (int i = 0; i < 8; i++) {
                FFMA2(acc2[i][0], a2.x, w2[i][0], acc2[i][0]);
                FFMA2(acc2[i][1], a2.y, w2[i][1], acc2[i][1]);
            }
            if (q < 63) {
                #pragma unroll
                for (int i = 7; i > 0; i--) { w2[i][0] = w2[i - 1][0]; w2[i][1] = w2[i - 1][1]; }
                int slot = (base - 1 - q) & 255;
                ulonglong2 wv = *(const ulonglong2*)(&v_s[slot * 64 + tx * 4]);
                w2[0][0] = wv.x; w2[0][1] = wv.y;
            }
        }
    }

    #pragma unroll
    for (int i = 0; i < 8; i++) {
        int t = t0 + ty * 8 + i;
        size_t off = ((size_t)b * NTOK + t) * D1 + c0 + tx * 4;
        float4 uv = *(const float4*)(u + off);
        float2 lo = *(float2*)(&acc2[i][0]);
        float2 hi = *(float2*)(&acc2[i][1]);
        __half2 ha = __floats2half2_rn(uv.x * lo.x, uv.y * lo.y);
        __half2 hb = __floats2half2_rn(uv.z * hi.x, uv.w * hi.y);
        *(uint2*)(yh + off) = make_uint2(*(uint32_t*)&ha, *(uint32_t*)&hb);
    }
}

// ---------------- launch ----------------
extern "C" void kernel_launch(void* const* d_in, const int* in_sizes, int n_in,
                              void* d_out, int out_size) {
    const float* x  = (const float*)d_in[0];
    const float* Wu = (const float*)d_in[1];
    const float* bu = (const float*)d_in[2];
    const float* Wv = (const float*)d_in[3];
    const float* bv = (const float*)d_in[4];
    const float* Wo = (const float*)d_in[5];
    const float* bo = (const float*)d_in[6];
    const float* Wp = (const float*)d_in[7];
    const float* bp = (const float*)d_in[8];
    const float* W1 = (const float*)d_in[9];
    const float* b1 = (const float*)d_in[10];
    const float* W2 = (const float*)d_in[11];
    const float* b2 = (const float*)d_in[12];
    const float* W3 = (const float*)d_in[13];
    const float* b3 = (const float*)d_in[14];
    const float* Wz = (const float*)d_in[15];
    const float* bz = (const float*)d_in[16];
    float* out = (float*)d_out;

    float *u, *v, *arr;
    __half *xnh, *yh, *Wuh, *Wvh, *Woh, *W1h, *W2h, *W3h, *Wzh;
    cudaGetSymbolAddress((void**)&u,    g_u);
    cudaGetSymbolAddress((void**)&v,    g_v);
    cudaGetSymbolAddress((void**)&arr,  g_arr);
    cudaGetSymbolAddress((void**)&xnh,  g_xnh);
    cudaGetSymbolAddress((void**)&yh,   g_yh);
    cudaGetSymbolAddress((void**)&Wuh,  g_Wuh);
    cudaGetSymbolAddress((void**)&Wvh,  g_Wvh);
    cudaGetSymbolAddress((void**)&Woh,  g_Woh);
    cudaGetSymbolAddress((void**)&W1h,  g_W1h);
    cudaGetSymbolAddress((void**)&W2h,  g_W2h);
    cudaGetSymbolAddress((void**)&W3h,  g_W3h);
    cudaGetSymbolAddress((void**)&Wzh,  g_Wzh);

    cudaFuncSetAttribute(hgemm_kernel<1>, cudaFuncAttributeMaxDynamicSharedMemorySize, GEMM_SMEM);
    cudaFuncSetAttribute(hgemm_kernel<3>, cudaFuncAttributeMaxDynamicSharedMemorySize, GEMM_SMEM);
    cudaFuncSetAttribute(conv_kernel,     cudaFuncAttributeMaxDynamicSharedMemorySize, CONV_SMEM);
    cudaFuncSetAttribute(coef_mlp_kernel, cudaFuncAttributeMaxDynamicSharedMemorySize, COEF_SMEM);

    // one-time lazy init of stream + events (deterministic; capture-safe)
    static cudaStream_t s1 = nullptr;
    static cudaEvent_t ev0 = nullptr, evF = nullptr, evC = nullptr;
    if (!s1) {
        cudaStreamCreateWithFlags(&s1, cudaStreamNonBlocking);
        cudaEventCreateWithFlags(&ev0, cudaEventDisableTiming);
        cudaEventCreateWithFlags(&evF, cudaEventDisableTiming);
        cudaEventCreateWithFlags(&evC, cudaEventDisableTiming);
    }

    cudaEventRecord(ev0, 0);            // fork point on capturing stream
    cudaStreamWaitEvent(s1, ev0, 0);

    // s1: weight conversion -> (evF) -> fused coefficient MLP -> (evC)
    f2h_all_kernel<<<2816, 256, 0, s1>>>(Wu, Wv, Wo, W1, W2, W3, Wz,
                                         Wuh, Wvh, Woh, W1h, W2h, W3h, Wzh);
    cudaEventRecord(evF, s1);
    coef_mlp_kernel<<<NTOK / 16, 256, COEF_SMEM, s1>>>(Wp, bp, W1h, b1, W2h, b2,
                                                       W3h, b3, Wzh, bz, arr);
    cudaEventRecord(evC, s1);

    // s0: main-path norm (independent of weights)
    srms_kernel<<<ROWS, 128>>>(x, xnh);

    // s0: u/v projections need converted weights (evF), overlap with coef on s1
    cudaStreamWaitEvent(0, evF, 0);
    hgemm_kernel<1><<<dim3(D1 / 128, ROWS / 128), 256, GEMM_SMEM>>>(xnh, Wuh, bu, nullptr, u, ROWS, D1, DDIM);
    hgemm_kernel<1><<<dim3(D1 / 128, ROWS / 128), 256, GEMM_SMEM>>>(xnh, Wvh, bv, nullptr, v, ROWS, D1, DDIM);

    // s0: conv needs arr (evC); single balanced 1024-block launch
    cudaStreamWaitEvent(0, evC, 0);
    conv_kernel<<<dim3(NTOK / 128, D1 / 64, NB), 256, CONV_SMEM>>>(v, arr, u, yh);

    // output projection + bias + residual
    hgemm_kernel<3><<<dim3(DDIM / 128, ROWS / 128), 256, GEMM_SMEM>>>(yh, Woh, bo, x, out, ROWS, DDIM, D1);
}